// round 2
// baseline (speedup 1.0000x reference)
#include <cuda_runtime.h>
#include <math.h>

#define Bb   64
#define Nn   2048
#define Cc   512
#define Ee   32
#define E2c  64
#define Ac   8
#define INc  512
#define Hc   64

// -------------------- device scratch (static; allocation-free at launch) ---
__device__ float g_K      [(long long)Bb*Nn*Cc];   // 256 MB
__device__ float g_node_t [(long long)Bb*Nn*INc];  // 256 MB
__device__ float g_logits [(long long)Bb*Nn*INc];  // 256 MB
__device__ float g_edge_t [(long long)Bb*Nn*INc];  // 256 MB
__device__ float g_H1     [(long long)Bb*Nn*Hc];   // 32 MB
__device__ float g_H2     [(long long)Bb*Nn*Hc];   // 32 MB
__device__ float g_val    [(long long)Bb*Nn*Ee];   // 16 MB
__device__ float g_Q      [Bb*Cc];
__device__ float g_pmax   [Bb*INc*16];
__device__ float g_psum   [Bb*INc*16];
__device__ float2 g_stat  [Bb*INc];
__device__ float g_thr    [Bb*INc];

// -------------------- generic fp32 SGEMM: C = A(MxK) * W(NxK)^T + bias -----
// M % 128 == 0, Ncols % 128 == 0, Kd % 16 == 0 (true for all call sites)
__global__ __launch_bounds__(256, 2)
void sgemm_nt(const float* __restrict__ Ap, const float* __restrict__ Wp,
              const float* __restrict__ bias, float* __restrict__ Cp,
              int M, int Ncols, int Kd)
{
    __shared__ __align__(16) float As[16][128];
    __shared__ __align__(16) float Bs[16][128];
    const int tid = threadIdx.x;
    const int bx = blockIdx.x, by = blockIdx.y;
    const int tx = tid & 15, ty = tid >> 4;
    const int lr = tid >> 2;            // 0..63
    const int lk = (tid & 3) * 4;       // 0,4,8,12

    const float* Aptr  = Ap + (long long)(by * 128 + lr) * Kd + lk;
    const float* Aptr2 = Aptr + (long long)64 * Kd;
    const float* Wptr  = Wp + (long long)(bx * 128 + lr) * Kd + lk;
    const float* Wptr2 = Wptr + (long long)64 * Kd;

    float acc[8][8];
#pragma unroll
    for (int i = 0; i < 8; i++)
#pragma unroll
        for (int j = 0; j < 8; j++) acc[i][j] = 0.f;

    for (int k0 = 0; k0 < Kd; k0 += 16) {
        float4 a0 = *(const float4*)(Aptr  + k0);
        float4 a1 = *(const float4*)(Aptr2 + k0);
        float4 w0 = *(const float4*)(Wptr  + k0);
        float4 w1 = *(const float4*)(Wptr2 + k0);
        __syncthreads();
        As[lk+0][lr]    = a0.x; As[lk+1][lr]    = a0.y; As[lk+2][lr]    = a0.z; As[lk+3][lr]    = a0.w;
        As[lk+0][lr+64] = a1.x; As[lk+1][lr+64] = a1.y; As[lk+2][lr+64] = a1.z; As[lk+3][lr+64] = a1.w;
        Bs[lk+0][lr]    = w0.x; Bs[lk+1][lr]    = w0.y; Bs[lk+2][lr]    = w0.z; Bs[lk+3][lr]    = w0.w;
        Bs[lk+0][lr+64] = w1.x; Bs[lk+1][lr+64] = w1.y; Bs[lk+2][lr+64] = w1.z; Bs[lk+3][lr+64] = w1.w;
        __syncthreads();
#pragma unroll
        for (int kk = 0; kk < 16; kk++) {
            float4 av0 = *(const float4*)&As[kk][ty*8];
            float4 av1 = *(const float4*)&As[kk][ty*8+4];
            float4 bv0 = *(const float4*)&Bs[kk][tx*8];
            float4 bv1 = *(const float4*)&Bs[kk][tx*8+4];
            float a[8] = {av0.x,av0.y,av0.z,av0.w,av1.x,av1.y,av1.z,av1.w};
            float b[8] = {bv0.x,bv0.y,bv0.z,bv0.w,bv1.x,bv1.y,bv1.z,bv1.w};
#pragma unroll
            for (int i = 0; i < 8; i++)
#pragma unroll
                for (int j = 0; j < 8; j++)
                    acc[i][j] = fmaf(a[i], b[j], acc[i][j]);
        }
    }

    const int col0 = bx * 128 + tx * 8;
    float bl[8];
#pragma unroll
    for (int j = 0; j < 8; j++) bl[j] = bias ? bias[col0 + j] : 0.f;
#pragma unroll
    for (int i = 0; i < 8; i++) {
        long long row = (long long)by * 128 + ty * 8 + i;
        float4 o0 = make_float4(acc[i][0]+bl[0], acc[i][1]+bl[1], acc[i][2]+bl[2], acc[i][3]+bl[3]);
        float4 o1 = make_float4(acc[i][4]+bl[4], acc[i][5]+bl[5], acc[i][6]+bl[6], acc[i][7]+bl[7]);
        *(float4*)(Cp + row * Ncols + col0)     = o0;
        *(float4*)(Cp + row * Ncols + col0 + 4) = o1;
    }
}

// -------------------- Q = node[:, 0, :] @ Wq_w^T + Wq_b --------------------
__global__ __launch_bounds__(256)
void q_kernel(const float* __restrict__ node, const float* __restrict__ Wq_w,
              const float* __restrict__ Wq_b)
{
    __shared__ __align__(16) float xs[512];
    const int b = blockIdx.x, tid = threadIdx.x;
    const float* xr = node + (long long)b * Nn * Cc;
    xs[tid]       = xr[tid];
    xs[tid + 256] = xr[tid + 256];
    __syncthreads();
    const float4* x4 = (const float4*)xs;
    for (int j = tid; j < 512; j += 256) {
        const float4* w4 = (const float4*)(Wq_w + (long long)j * 512);
        float acc = Wq_b[j];
#pragma unroll 8
        for (int k = 0; k < 128; k++) {
            float4 w = w4[k], x = x4[k];
            acc += w.x*x.x + w.y*x.y + w.z*x.z + w.w*x.w;
        }
        g_Q[b * 512 + j] = acc;
    }
}

// -------------------- val = selu(rho(QKlo*ew) + QKhi*emb1 + emb2) ----------
__global__ __launch_bounds__(256)
void val_kernel(const float* __restrict__ edge, const float* __restrict__ emb1,
                const float* __restrict__ emb2, const float* __restrict__ Wew)
{
    __shared__ float Qs[512];
    __shared__ float Wews[32 * 32];
    __shared__ float er[4][32];
    __shared__ float qks[4][64];
    const int tid = threadIdx.x;
    const long long row0 = (long long)blockIdx.x * 4;
    const int b = (int)(row0 >> 11);

    Qs[tid]       = g_Q[b * 512 + tid];
    Qs[tid + 256] = g_Q[b * 512 + tid + 256];
    for (int i = tid; i < 1024; i += 256) Wews[i] = Wew[i];
    if (tid < 128) er[tid >> 5][tid & 31] = edge[(row0 + (tid >> 5)) * 32 + (tid & 31)];
    __syncthreads();

    const int ry = tid >> 6;
    const int e2 = tid & 63;
    const long long row = row0 + ry;
    const float* Krow = g_K + row * 512;
    float qk = 0.f;
#pragma unroll
    for (int a = 0; a < 8; a++) qk += Qs[a * 64 + e2] * Krow[a * 64 + e2];
    qks[ry][e2] = qk;
    __syncthreads();

    if (e2 < 32) {
        float ew = 0.f;
#pragma unroll
        for (int j = 0; j < 32; j++) ew += er[ry][j] * Wews[e2 * 32 + j];
        float x = qk * ew;                       // qk = QK[e2], e2 < 32
        float r = (x > 0.f) ? sqrtf(x) : -sqrtf(-x);   // rho
        float hi = qks[ry][32 + e2];
        float v = r + hi * emb1[row * 32 + e2] + emb2[row * 32 + e2];
        const float sc = 1.0507009873554805f, al = 1.6732632423543772f;
        float s = (v > 0.f) ? sc * v : sc * al * (expf(v) - 1.f);
        g_val[row * 32 + e2] = s;
    }
}

// -------------------- H1 = gelu(val@Wa_w1^T), H2 = gelu(val@et_w1^T + b1) --
__global__ __launch_bounds__(128)
void h_kernel(const float* __restrict__ Wa_w1, const float* __restrict__ et_w1,
              const float* __restrict__ et_b1)
{
    __shared__ float W1s[32 * 64];  // transposed: [e][h]
    __shared__ float W2s[32 * 64];
    __shared__ float b1s[64];
    __shared__ float vs[8][32];
    const int tid = threadIdx.x;
    for (int i = tid; i < 2048; i += 128) {
        int h = i >> 5, e = i & 31;
        W1s[e * 64 + h] = Wa_w1[i];
        W2s[e * 64 + h] = et_w1[i];
    }
    if (tid < 64) b1s[tid] = et_b1[tid];
    const long long row0 = (long long)blockIdx.x * 8;
    for (int i = tid; i < 256; i += 128) vs[i >> 5][i & 31] = g_val[row0 * 32 + i];
    __syncthreads();

    const int h = tid & 63;
    const int which = tid >> 6;
    const float* Wp = which ? W2s : W1s;
    const float bb = which ? b1s[h] : 0.f;
    float* dst = which ? g_H2 : g_H1;
#pragma unroll 1
    for (int r = 0; r < 8; r++) {
        float acc = bb;
#pragma unroll
        for (int e = 0; e < 32; e++) acc = fmaf(vs[r][e], Wp[e * 64 + h], acc);
        float g = 0.5f * acc * (1.f + erff(acc * 0.70710678118654752f));
        dst[(row0 + r) * 64 + h] = g;
    }
}

// -------------------- softmax over n (per b, channel): stage 1 -------------
__global__ __launch_bounds__(128)
void soft_stage1()
{
    const int b = blockIdx.z, cb = blockIdx.y, nz = blockIdx.x;
    const int c = cb * 128 + threadIdx.x;
    const int n0 = 1 + nz * 128;
    const int n1 = min(2048, n0 + 128);
    const float* base = g_logits + ((long long)b * 2048) * 512 + c;
    float m = -1e30f, s = 0.f;
    for (int n = n0; n < n1; n++) {
        float x = base[(long long)n * 512];
        if (x > m) { s = s * expf(m - x) + 1.f; m = x; }
        else       { s += expf(x - m); }
    }
    g_pmax[(b * 512 + c) * 16 + nz] = m;
    g_psum[(b * 512 + c) * 16 + nz] = s;
}

__global__ __launch_bounds__(256)
void soft_stage2()
{
    const int i = blockIdx.x * 256 + threadIdx.x;   // b*512 + c
    float m = -1e30f;
#pragma unroll
    for (int k = 0; k < 16; k++) m = fmaxf(m, g_pmax[i * 16 + k]);
    float s = 0.f;
#pragma unroll
    for (int k = 0; k < 16; k++) s += g_psum[i * 16 + k] * expf(g_pmax[i * 16 + k] - m);
    g_stat[i] = make_float2(m, 1.f / s);
}

// -------------------- tmp = (node_t + edge_t)*alpha; colmax |tmp| ----------
__global__ __launch_bounds__(128)
void pass1(float* __restrict__ d_tmp)
{
    const int b = blockIdx.z, cb = blockIdx.y, nz = blockIdx.x;
    const int c = cb * 128 + threadIdx.x;
    const float2 st = g_stat[b * 512 + c];
    const int n0 = 1 + nz * 128;
    const int n1 = min(2048, n0 + 128);
    float mm = 0.f;
    for (int n = n0; n < n1; n++) {
        long long ro = ((long long)(b * 2048 + n)) * 512 + c;
        float alpha = expf(g_logits[ro] - st.x) * st.y;
        float t = (g_node_t[ro] + g_edge_t[ro]) * alpha;
        d_tmp[((long long)(b * 2047 + n - 1)) * 512 + c] = t;
        mm = fmaxf(mm, fabsf(t));
    }
    g_pmax[(b * 512 + c) * 16 + nz] = mm;
}

__global__ __launch_bounds__(256)
void pass1b()
{
    const int i = blockIdx.x * 256 + threadIdx.x;
    float m = 0.f;
#pragma unroll
    for (int k = 0; k < 16; k++) m = fmaxf(m, g_pmax[i * 16 + k]);
    g_thr[i] = m * 0.1f;    // MASK_RATIO = 10
}

// -------------------- mask + column sum ------------------------------------
__global__ __launch_bounds__(128)
void pass2(float* __restrict__ d_tmp)
{
    const int b = blockIdx.z, cb = blockIdx.y, nz = blockIdx.x;
    const int c = cb * 128 + threadIdx.x;
    const float thr = g_thr[b * 512 + c];
    const int n0 = 1 + nz * 128;
    const int n1 = min(2048, n0 + 128);
    float s = 0.f;
    for (int n = n0; n < n1; n++) {
        long long idx = ((long long)(b * 2047 + n - 1)) * 512 + c;
        float t = d_tmp[idx];
        t = (fabsf(t) >= thr) ? t : 0.f;
        d_tmp[idx] = t;
        s += t;
    }
    g_psum[(b * 512 + c) * 16 + nz] = s;
}

__global__ __launch_bounds__(256)
void pass2b(float* __restrict__ outp)
{
    const int i = blockIdx.x * 256 + threadIdx.x;
    float s = 0.f;
#pragma unroll
    for (int k = 0; k < 16; k++) s += g_psum[i * 16 + k];
    outp[i] = s;
}

// ---------------------------------------------------------------------------
extern "C" void kernel_launch(void* const* d_in, const int* in_sizes, int n_in,
                              void* d_out, int out_size)
{
    const float* node  = (const float*)d_in[0];
    const float* edge  = (const float*)d_in[1];
    const float* emb1  = (const float*)d_in[2];
    const float* emb2  = (const float*)d_in[3];
    const float* Wq_w  = (const float*)d_in[4];
    const float* Wq_b  = (const float*)d_in[5];
    const float* Wk_w  = (const float*)d_in[6];
    const float* Wk_b  = (const float*)d_in[7];
    const float* Wew_w = (const float*)d_in[8];
    const float* Wa_w1 = (const float*)d_in[9];
    const float* Wa_w2 = (const float*)d_in[10];
    const float* nt_w  = (const float*)d_in[11];
    const float* nt_b  = (const float*)d_in[12];
    const float* et_w1 = (const float*)d_in[13];
    const float* et_b1 = (const float*)d_in[14];
    const float* et_w2 = (const float*)d_in[15];
    const float* et_b2 = (const float*)d_in[16];

    float* outp  = (float*)d_out;            // (B, IN) first
    float* d_tmp = outp + Bb * INc;          // then (B, N-1, IN)

    void *pK, *pNT, *pLG, *pET, *pH1, *pH2;
    cudaGetSymbolAddress(&pK,  g_K);
    cudaGetSymbolAddress(&pNT, g_node_t);
    cudaGetSymbolAddress(&pLG, g_logits);
    cudaGetSymbolAddress(&pET, g_edge_t);
    cudaGetSymbolAddress(&pH1, g_H1);
    cudaGetSymbolAddress(&pH2, g_H2);

    const int M = Bb * Nn;                   // 131072
    dim3 gBig(INc / 128, M / 128);           // (4, 1024)

    // 1) K = node @ Wk^T + bk   (big GEMM #1)
    sgemm_nt<<<gBig, 256>>>(node, Wk_w, Wk_b, (float*)pK, M, INc, Cc);
    // 2) Q projection (first node of each batch)
    q_kernel<<<Bb, 256>>>(node, Wq_w, Wq_b);
    // 3) val = selu(rho(QK_lo*ew) + QK_hi*emb1 + emb2)
    val_kernel<<<M / 4, 256>>>(edge, emb1, emb2, Wew_w);
    // 4) hidden layers of both small FFNs (gelu)
    h_kernel<<<M / 8, 128>>>(Wa_w1, et_w1, et_b1);
    // 5) logits = H1 @ Wa_w2^T ; edge_t = H2 @ et_w2^T + et_b2
    sgemm_nt<<<gBig, 256>>>((const float*)pH1, Wa_w2, nullptr, (float*)pLG, M, INc, Hc);
    sgemm_nt<<<gBig, 256>>>((const float*)pH2, et_w2, et_b2,   (float*)pET, M, INc, Hc);
    // 6) node_t = node @ nt_w^T + nt_b   (big GEMM #2)
    sgemm_nt<<<gBig, 256>>>(node, nt_w, nt_b, (float*)pNT, M, INc, Cc);
    // 7) softmax over n per (b, channel)
    soft_stage1<<<dim3(16, 4, Bb), 128>>>();
    soft_stage2<<<(Bb * INc) / 256, 256>>>();
    // 8) tmp (unmasked) + threshold
    pass1<<<dim3(16, 4, Bb), 128>>>(d_tmp);
    pass1b<<<(Bb * INc) / 256, 256>>>();
    // 9) mask in place + column sums -> out
    pass2<<<dim3(16, 4, Bb), 128>>>(d_tmp);
    pass2b<<<(Bb * INc) / 256, 256>>>(outp);
}

// round 4
// speedup vs baseline: 1.9800x; 1.9800x over previous
#include <cuda_runtime.h>
#include <math.h>
#include <stdint.h>

#define Bb   64
#define Nn   2048
#define Cc   512
#define Ee   32
#define Ac   8
#define INc  512
#define Hc   64

// -------------------- device scratch (static; allocation-free) -------------
__device__ float g_K      [(long long)Bb*Nn*Cc];
__device__ float g_node_t [(long long)Bb*Nn*INc];
__device__ float g_logits [(long long)Bb*Nn*INc];
__device__ float g_edge_t [(long long)Bb*Nn*INc];
__device__ float g_H1     [(long long)Bb*Nn*Hc];
__device__ float g_H2     [(long long)Bb*Nn*Hc];
__device__ float g_val    [(long long)Bb*Nn*Ee];
__device__ float g_Q      [Bb*Cc];
__device__ float g_pmax   [Bb*INc*16];
__device__ float g_psum   [Bb*INc*16];
__device__ float2 g_stat  [Bb*INc];
__device__ float g_thr    [Bb*INc];

// ========================== helpers ========================================
__device__ __forceinline__ uint32_t smem_u32(const void* p) {
    uint32_t a;
    asm("{ .reg .u64 t; cvta.to.shared.u64 t, %1; cvt.u32.u64 %0, t; }" : "=r"(a) : "l"(p));
    return a;
}
__device__ __forceinline__ uint32_t cvt2bf(float hi, float lo) {
    uint32_t r;
    asm("cvt.rn.bf16x2.f32 %0, %1, %2;" : "=r"(r) : "f"(hi), "f"(lo));
    return r;
}
// 8 fp32 -> hi bf16x8 (16B at addr), lo bf16x8 (16B at addr+10240)
__device__ __forceinline__ void split8(uint32_t addr, float4 a0, float4 a1) {
    uint32_t h0 = cvt2bf(a0.y, a0.x);
    uint32_t h1 = cvt2bf(a0.w, a0.z);
    uint32_t h2 = cvt2bf(a1.y, a1.x);
    uint32_t h3 = cvt2bf(a1.w, a1.z);
    float l0 = a0.x - __uint_as_float(h0 << 16);
    float l1 = a0.y - __uint_as_float(h0 & 0xffff0000u);
    float l2 = a0.z - __uint_as_float(h1 << 16);
    float l3 = a0.w - __uint_as_float(h1 & 0xffff0000u);
    float l4 = a1.x - __uint_as_float(h2 << 16);
    float l5 = a1.y - __uint_as_float(h2 & 0xffff0000u);
    float l6 = a1.z - __uint_as_float(h3 << 16);
    float l7 = a1.w - __uint_as_float(h3 & 0xffff0000u);
    uint32_t q0 = cvt2bf(l1, l0), q1 = cvt2bf(l3, l2);
    uint32_t q2 = cvt2bf(l5, l4), q3 = cvt2bf(l7, l6);
    asm volatile("st.shared.v4.b32 [%0], {%1,%2,%3,%4};" :: "r"(addr), "r"(h0), "r"(h1), "r"(h2), "r"(h3));
    asm volatile("st.shared.v4.b32 [%0], {%1,%2,%3,%4};" :: "r"(addr + 10240), "r"(q0), "r"(q1), "r"(q2), "r"(q3));
}

#define LDSM_X4(r0, r1, r2, r3, addr) \
    asm volatile("ldmatrix.sync.aligned.m8n8.x4.shared.b16 {%0,%1,%2,%3}, [%4];" \
        : "=r"(r0), "=r"(r1), "=r"(r2), "=r"(r3) : "r"(addr))

__device__ __forceinline__ void mma16816(float d[4], const uint32_t a[4], const uint32_t b[2]) {
    asm volatile("mma.sync.aligned.m16n8k16.row.col.f32.bf16.bf16.f32 "
        "{%0,%1,%2,%3},{%4,%5,%6,%7},{%8,%9},{%0,%1,%2,%3};"
        : "+f"(d[0]), "+f"(d[1]), "+f"(d[2]), "+f"(d[3])
        : "r"(a[0]), "r"(a[1]), "r"(a[2]), "r"(a[3]), "r"(b[0]), "r"(b[1]));
}

// ================= bf16x3-split mma.sync GEMM: C = A(MxK) W(NxK)^T + b =====
// block tile 128x128, k-chunk 32. Kd % 32 == 0; M, Ncols % 128 == 0.
// smem layout (bytes): A_hi[128*80] | A_lo | B_hi | B_lo   (rows padded to 80B)
__global__ __launch_bounds__(256, 2)
void mma_gemm(const float* __restrict__ Ap, const float* __restrict__ Wp,
              const float* __restrict__ bias, float* __restrict__ Cp,
              int Ncols, int Kd)
{
    __shared__ __align__(128) uint8_t smem_raw[40960];
    const uint32_t SA = smem_u32(smem_raw);        // A_hi
    const uint32_t SB = SA + 20480;                // B_hi
    const int tid = threadIdx.x;
    const int wid = tid >> 5;
    const int lid = tid & 31;
    const int warp_m = wid & 3;        // 4 warps over M (32 rows each)
    const int warp_n = wid >> 2;       // 2 warps over N (64 cols each)

    const long long row0 = (long long)blockIdx.y * 128;
    const int col0 = blockIdx.x * 128;

    // --- gmem load mapping: each thread loads 16 A floats + 16 B floats/chunk
    const int lr = tid >> 1;           // 0..127
    const int kh = tid & 1;            // k-half (16 floats)
    const float* Arow = Ap + (row0 + lr) * (long long)Kd + kh * 16;
    const float* Brow = Wp + (long long)(col0 + lr) * Kd + kh * 16;
    const uint32_t sAst = SA + (uint32_t)lr * 80 + (uint32_t)kh * 32;
    const uint32_t sBst = SB + (uint32_t)lr * 80 + (uint32_t)kh * 32;

    // --- ldmatrix lane addresses (byte offsets, khalf*32 added in loop)
    // A tile mt: rows m = warp_m*32 + mt*16 + (l&7) + ((l>>3)&1)*8 ; kgran=(l>>4)&1
    uint32_t aoff[2];
#pragma unroll
    for (int mt = 0; mt < 2; mt++) {
        int rowm = warp_m * 32 + mt * 16 + (lid & 7) + ((lid >> 3) & 1) * 8;
        aoff[mt] = SA + (uint32_t)rowm * 80 + (uint32_t)((lid >> 4) & 1) * 16;
    }
    // B tile-pair ntp: n = warp_n*64 + ntp*16 + (l&7) + ((l>>4)&1)*8 ; kgran=(l>>3)&1
    uint32_t boff[4];
#pragma unroll
    for (int ntp = 0; ntp < 4; ntp++) {
        int rown = warp_n * 64 + ntp * 16 + (lid & 7) + ((lid >> 4) & 1) * 8;
        boff[ntp] = SB + (uint32_t)rown * 80 + (uint32_t)((lid >> 3) & 1) * 16;
    }

    float acc[2][8][4];
#pragma unroll
    for (int i = 0; i < 2; i++)
#pragma unroll
        for (int j = 0; j < 8; j++)
#pragma unroll
            for (int q = 0; q < 4; q++) acc[i][j][q] = 0.f;

    const int nchunk = Kd >> 5;
    for (int ch = 0; ch < nchunk; ch++) {
        const int k0 = ch * 32;
        float4 a00 = *(const float4*)(Arow + k0);
        float4 a01 = *(const float4*)(Arow + k0 + 4);
        float4 a10 = *(const float4*)(Arow + k0 + 8);
        float4 a11 = *(const float4*)(Arow + k0 + 12);
        float4 b00 = *(const float4*)(Brow + k0);
        float4 b01 = *(const float4*)(Brow + k0 + 4);
        float4 b10 = *(const float4*)(Brow + k0 + 8);
        float4 b11 = *(const float4*)(Brow + k0 + 12);
        __syncthreads();
        split8(sAst,      a00, a01);
        split8(sAst + 16, a10, a11);
        split8(sBst,      b00, b01);
        split8(sBst + 16, b10, b11);
        __syncthreads();

#pragma unroll
        for (int khalf = 0; khalf < 2; khalf++) {
            const uint32_t kb = (uint32_t)khalf * 32;
            uint32_t Ah[2][4], Al[2][4];
#pragma unroll
            for (int mt = 0; mt < 2; mt++) {
                LDSM_X4(Ah[mt][0], Ah[mt][1], Ah[mt][2], Ah[mt][3], aoff[mt] + kb);
                LDSM_X4(Al[mt][0], Al[mt][1], Al[mt][2], Al[mt][3], aoff[mt] + kb + 10240);
            }
#pragma unroll
            for (int ntp = 0; ntp < 4; ntp++) {
                uint32_t Bh[4], Bl[4];
                LDSM_X4(Bh[0], Bh[1], Bh[2], Bh[3], boff[ntp] + kb);
                LDSM_X4(Bl[0], Bl[1], Bl[2], Bl[3], boff[ntp] + kb + 10240);
#pragma unroll
                for (int mt = 0; mt < 2; mt++) {
#pragma unroll
                    for (int nt2 = 0; nt2 < 2; nt2++) {
                        float* d = acc[mt][ntp * 2 + nt2];
                        mma16816(d, Ah[mt], &Bh[nt2 * 2]);   // hi*hi
                        mma16816(d, Ah[mt], &Bl[nt2 * 2]);   // hi*lo
                        mma16816(d, Al[mt], &Bh[nt2 * 2]);   // lo*hi
                    }
                }
            }
        }
    }

    // --- epilogue
    const int g = lid >> 2;            // 0..7
    const int t = lid & 3;             // 0..3
#pragma unroll
    for (int mt = 0; mt < 2; mt++) {
        long long rA = row0 + warp_m * 32 + mt * 16 + g;
        long long rB = rA + 8;
#pragma unroll
        for (int nt = 0; nt < 8; nt++) {
            int col = col0 + warp_n * 64 + nt * 8 + 2 * t;
            float b0 = bias ? bias[col] : 0.f;
            float b1 = bias ? bias[col + 1] : 0.f;
            float* d = acc[mt][nt];
            *(float2*)(Cp + rA * Ncols + col) = make_float2(d[0] + b0, d[1] + b1);
            *(float2*)(Cp + rB * Ncols + col) = make_float2(d[2] + b0, d[3] + b1);
        }
    }
}

// -------------------- Q = node[:, 0, :] @ Wq_w^T + Wq_b --------------------
__global__ __launch_bounds__(256)
void q_kernel(const float* __restrict__ node, const float* __restrict__ Wq_w,
              const float* __restrict__ Wq_b)
{
    __shared__ __align__(16) float xs[512];
    const int b = blockIdx.x, tid = threadIdx.x;
    const float* xr = node + (long long)b * Nn * Cc;
    xs[tid]       = xr[tid];
    xs[tid + 256] = xr[tid + 256];
    __syncthreads();
    const float4* x4 = (const float4*)xs;
    for (int j = tid; j < 512; j += 256) {
        const float4* w4 = (const float4*)(Wq_w + (long long)j * 512);
        float acc = Wq_b[j];
#pragma unroll 8
        for (int k = 0; k < 128; k++) {
            float4 w = w4[k], x = x4[k];
            acc += w.x*x.x + w.y*x.y + w.z*x.z + w.w*x.w;
        }
        g_Q[b * 512 + j] = acc;
    }
}

// -------------------- val = selu(rho(QKlo*ew) + QKhi*emb1 + emb2) ----------
__global__ __launch_bounds__(256)
void val_kernel(const float* __restrict__ edge, const float* __restrict__ emb1,
                const float* __restrict__ emb2, const float* __restrict__ Wew)
{
    __shared__ float Qs[512];
    __shared__ float Wews[32 * 32];
    __shared__ float er[4][32];
    __shared__ float qks[4][64];
    const int tid = threadIdx.x;
    const long long row0 = (long long)blockIdx.x * 4;
    const int b = (int)(row0 >> 11);

    Qs[tid]       = g_Q[b * 512 + tid];
    Qs[tid + 256] = g_Q[b * 512 + tid + 256];
    for (int i = tid; i < 1024; i += 256) Wews[i] = Wew[i];
    if (tid < 128) er[tid >> 5][tid & 31] = edge[(row0 + (tid >> 5)) * 32 + (tid & 31)];
    __syncthreads();

    const int ry = tid >> 6;
    const int e2 = tid & 63;
    const long long row = row0 + ry;
    const float* Krow = g_K + row * 512;
    float qk = 0.f;
#pragma unroll
    for (int a = 0; a < 8; a++) qk += Qs[a * 64 + e2] * Krow[a * 64 + e2];
    qks[ry][e2] = qk;
    __syncthreads();

    if (e2 < 32) {
        float ew = 0.f;
#pragma unroll
        for (int j = 0; j < 32; j++) ew += er[ry][j] * Wews[e2 * 32 + j];
        float x = qk * ew;
        float rr = (x > 0.f) ? sqrtf(x) : -sqrtf(-x);
        float hi = qks[ry][32 + e2];
        float v = rr + hi * emb1[row * 32 + e2] + emb2[row * 32 + e2];
        const float sc = 1.0507009873554805f, al = 1.6732632423543772f;
        float s = (v > 0.f) ? sc * v : sc * al * (expf(v) - 1.f);
        g_val[row * 32 + e2] = s;
    }
}

// -------- H1 = gelu(val@Wa_w1^T), H2 = gelu(val@et_w1^T + b1) — W in regs ---
__global__ __launch_bounds__(128)
void h_kernel(const float* __restrict__ Wa_w1, const float* __restrict__ et_w1,
              const float* __restrict__ et_b1)
{
    __shared__ __align__(16) float vs[8][32];
    const int tid = threadIdx.x;
    const int h = tid & 63, which = tid >> 6;
    const float* Wrow = (which ? et_w1 : Wa_w1) + h * 32;
    float w[32];
#pragma unroll
    for (int e4 = 0; e4 < 8; e4++) {
        float4 t = *(const float4*)(Wrow + e4 * 4);
        w[e4*4] = t.x; w[e4*4+1] = t.y; w[e4*4+2] = t.z; w[e4*4+3] = t.w;
    }
    const float bb = which ? et_b1[h] : 0.f;
    const long long row0 = (long long)blockIdx.x * 8;
    ((float2*)vs)[tid] = ((const float2*)(g_val + row0 * 32))[tid];
    __syncthreads();

    float acc[8];
#pragma unroll
    for (int rr = 0; rr < 8; rr++) acc[rr] = bb;
#pragma unroll
    for (int e4 = 0; e4 < 8; e4++) {
#pragma unroll
        for (int rr = 0; rr < 8; rr++) {
            float4 v = *(const float4*)&vs[rr][e4 * 4];
            acc[rr] = fmaf(v.x, w[e4*4], acc[rr]);
            acc[rr] = fmaf(v.y, w[e4*4+1], acc[rr]);
            acc[rr] = fmaf(v.z, w[e4*4+2], acc[rr]);
            acc[rr] = fmaf(v.w, w[e4*4+3], acc[rr]);
        }
    }
    float* dst = which ? g_H2 : g_H1;
#pragma unroll
    for (int rr = 0; rr < 8; rr++) {
        float a = acc[rr];
        float g = 0.5f * a * (1.f + erff(a * 0.70710678118654752f));
        dst[(row0 + rr) * 64 + h] = g;
    }
}

// -------------------- softmax over n (per b, channel) ----------------------
__global__ __launch_bounds__(128)
void soft_stage1()
{
    const int b = blockIdx.z, cb = blockIdx.y, nz = blockIdx.x;
    const int c = cb * 128 + threadIdx.x;
    const int n0 = 1 + nz * 128;
    const int n1 = min(2048, n0 + 128);
    const float* base = g_logits + ((long long)b * 2048) * 512 + c;
    float m = -1e30f, s = 0.f;
    for (int n = n0; n < n1; n++) {
        float x = base[(long long)n * 512];
        if (x > m) { s = s * expf(m - x) + 1.f; m = x; }
        else       { s += expf(x - m); }
    }
    g_pmax[(b * 512 + c) * 16 + nz] = m;
    g_psum[(b * 512 + c) * 16 + nz] = s;
}

__global__ __launch_bounds__(256)
void soft_stage2()
{
    const int i = blockIdx.x * 256 + threadIdx.x;
    float m = -1e30f;
#pragma unroll
    for (int k = 0; k < 16; k++) m = fmaxf(m, g_pmax[i * 16 + k]);
    float s = 0.f;
#pragma unroll
    for (int k = 0; k < 16; k++) s += g_psum[i * 16 + k] * expf(g_pmax[i * 16 + k] - m);
    g_stat[i] = make_float2(m, 1.f / s);
}

// -------------------- tmp = (node_t + edge_t)*alpha; colmax |tmp| ----------
__global__ __launch_bounds__(128)
void pass1(float* __restrict__ d_tmp)
{
    const int b = blockIdx.z, cb = blockIdx.y, nz = blockIdx.x;
    const int c = cb * 128 + threadIdx.x;
    const float2 st = g_stat[b * 512 + c];
    const int n0 = 1 + nz * 128;
    const int n1 = min(2048, n0 + 128);
    float mm = 0.f;
    for (int n = n0; n < n1; n++) {
        long long ro = ((long long)(b * 2048 + n)) * 512 + c;
        float alpha = expf(g_logits[ro] - st.x) * st.y;
        float t = (g_node_t[ro] + g_edge_t[ro]) * alpha;
        d_tmp[((long long)(b * 2047 + n - 1)) * 512 + c] = t;
        mm = fmaxf(mm, fabsf(t));
    }
    g_pmax[(b * 512 + c) * 16 + nz] = mm;
}

__global__ __launch_bounds__(256)
void pass1b()
{
    const int i = blockIdx.x * 256 + threadIdx.x;
    float m = 0.f;
#pragma unroll
    for (int k = 0; k < 16; k++) m = fmaxf(m, g_pmax[i * 16 + k]);
    g_thr[i] = m * 0.1f;
}

// -------------------- mask + column sum ------------------------------------
__global__ __launch_bounds__(128)
void pass2(float* __restrict__ d_tmp)
{
    const int b = blockIdx.z, cb = blockIdx.y, nz = blockIdx.x;
    const int c = cb * 128 + threadIdx.x;
    const float thr = g_thr[b * 512 + c];
    const int n0 = 1 + nz * 128;
    const int n1 = min(2048, n0 + 128);
    float s = 0.f;
    for (int n = n0; n < n1; n++) {
        long long idx = ((long long)(b * 2047 + n - 1)) * 512 + c;
        float t = d_tmp[idx];
        t = (fabsf(t) >= thr) ? t : 0.f;
        d_tmp[idx] = t;
        s += t;
    }
    g_psum[(b * 512 + c) * 16 + nz] = s;
}

__global__ __launch_bounds__(256)
void pass2b(float* __restrict__ outp)
{
    const int i = blockIdx.x * 256 + threadIdx.x;
    float s = 0.f;
#pragma unroll
    for (int k = 0; k < 16; k++) s += g_psum[i * 16 + k];
    outp[i] = s;
}

// ---------------------------------------------------------------------------
extern "C" void kernel_launch(void* const* d_in, const int* in_sizes, int n_in,
                              void* d_out, int out_size)
{
    const float* node  = (const float*)d_in[0];
    const float* edge  = (const float*)d_in[1];
    const float* emb1  = (const float*)d_in[2];
    const float* emb2  = (const float*)d_in[3];
    const float* Wq_w  = (const float*)d_in[4];
    const float* Wq_b  = (const float*)d_in[5];
    const float* Wk_w  = (const float*)d_in[6];
    const float* Wk_b  = (const float*)d_in[7];
    const float* Wew_w = (const float*)d_in[8];
    const float* Wa_w1 = (const float*)d_in[9];
    const float* Wa_w2 = (const float*)d_in[10];
    const float* nt_w  = (const float*)d_in[11];
    const float* nt_b  = (const float*)d_in[12];
    const float* et_w1 = (const float*)d_in[13];
    const float* et_b1 = (const float*)d_in[14];
    const float* et_w2 = (const float*)d_in[15];
    const float* et_b2 = (const float*)d_in[16];

    float* outp  = (float*)d_out;            // (B, IN) first
    float* d_tmp = outp + Bb * INc;          // then (B, N-1, IN)

    void *pK, *pNT, *pLG, *pET, *pH1, *pH2;
    cudaGetSymbolAddress(&pK,  g_K);
    cudaGetSymbolAddress(&pNT, g_node_t);
    cudaGetSymbolAddress(&pLG, g_logits);
    cudaGetSymbolAddress(&pET, g_edge_t);
    cudaGetSymbolAddress(&pH1, g_H1);
    cudaGetSymbolAddress(&pH2, g_H2);

    const int M = Bb * Nn;                   // 131072
    dim3 gBig(INc / 128, M / 128);           // (4, 1024)

    // 1) K = node @ Wk^T + bk
    mma_gemm<<<gBig, 256>>>(node, Wk_w, Wk_b, (float*)pK, INc, Cc);
    // 2) Q projection
    q_kernel<<<Bb, 256>>>(node, Wq_w, Wq_b);
    // 3) val
    val_kernel<<<M / 4, 256>>>(edge, emb1, emb2, Wew_w);
    // 4) hidden layers (gelu)
    h_kernel<<<M / 8, 128>>>(Wa_w1, et_w1, et_b1);
    // 5) logits / edge_t (K = 64)
    mma_gemm<<<gBig, 256>>>((const float*)pH1, Wa_w2, nullptr, (float*)pLG, INc, Hc);
    mma_gemm<<<gBig, 256>>>((const float*)pH2, et_w2, et_b2,   (float*)pET, INc, Hc);
    // 6) node_t
    mma_gemm<<<gBig, 256>>>(node, nt_w, nt_b, (float*)pNT, INc, Cc);
    // 7) softmax over n
    soft_stage1<<<dim3(16, 4, Bb), 128>>>();
    soft_stage2<<<(Bb * INc) / 256, 256>>>();
    // 8) tmp + threshold
    pass1<<<dim3(16, 4, Bb), 128>>>(d_tmp);
    pass1b<<<(Bb * INc) / 256, 256>>>();
    // 9) mask + column sums
    pass2<<<dim3(16, 4, Bb), 128>>>(d_tmp);
    pass2b<<<(Bb * INc) / 256, 256>>>(outp);
}

// round 5
// speedup vs baseline: 2.6098x; 1.3181x over previous
#include <cuda_runtime.h>
#include <cuda_fp16.h>
#include <math.h>
#include <stdint.h>

#define Bb   64
#define Nn   2048
#define Cc   512
#define Ee   32
#define Ac   8
#define INc  512
#define Hc   64
#define Mtot (Bb*Nn)

// -------------------- device scratch (static; allocation-free) -------------
__device__ float g_sum    [(long long)Mtot*INc];   // node_t + edge_t (pre-alpha)
__device__ float g_logits [(long long)Mtot*INc];
__device__ float g_H12    [(long long)Mtot*128];   // [H1 | H2]
__device__ float g_QK     [(long long)Mtot*64];
__device__ float g_val    [(long long)Mtot*Ee];
__device__ float g_Weff   [Bb*64*512];
__device__ float g_beff   [Bb*64];
__device__ float g_Q      [Bb*512];
__device__ float g_W12    [128*32];
__device__ float g_b12    [128];
__device__ float g_Wsum   [512*576];
__device__ float g_bsum   [512];

// ========================== helpers ========================================
__device__ __forceinline__ uint32_t smem_u32(const void* p) {
    uint32_t a;
    asm("{ .reg .u64 t; cvta.to.shared.u64 t, %1; cvt.u32.u64 %0, t; }" : "=r"(a) : "l"(p));
    return a;
}
// 8 fp32 -> hi f16x8 (16B at addr), lo f16x8 (16B at addr+lo_off)
__device__ __forceinline__ void split8h(uint32_t addr, uint32_t lo_off, float4 a0, float4 a1) {
    __half2 h0 = __float22half2_rn(make_float2(a0.x, a0.y));
    __half2 h1 = __float22half2_rn(make_float2(a0.z, a0.w));
    __half2 h2 = __float22half2_rn(make_float2(a1.x, a1.y));
    __half2 h3 = __float22half2_rn(make_float2(a1.z, a1.w));
    float2 f0 = __half22float2(h0), f1 = __half22float2(h1);
    float2 f2 = __half22float2(h2), f3 = __half22float2(h3);
    __half2 l0 = __float22half2_rn(make_float2(a0.x - f0.x, a0.y - f0.y));
    __half2 l1 = __float22half2_rn(make_float2(a0.z - f1.x, a0.w - f1.y));
    __half2 l2 = __float22half2_rn(make_float2(a1.x - f2.x, a1.y - f2.y));
    __half2 l3 = __float22half2_rn(make_float2(a1.z - f3.x, a1.w - f3.y));
    uint32_t u0 = *(uint32_t*)&h0, u1 = *(uint32_t*)&h1, u2 = *(uint32_t*)&h2, u3 = *(uint32_t*)&h3;
    uint32_t v0 = *(uint32_t*)&l0, v1 = *(uint32_t*)&l1, v2 = *(uint32_t*)&l2, v3 = *(uint32_t*)&l3;
    asm volatile("st.shared.v4.b32 [%0], {%1,%2,%3,%4};" :: "r"(addr), "r"(u0), "r"(u1), "r"(u2), "r"(u3));
    asm volatile("st.shared.v4.b32 [%0], {%1,%2,%3,%4};" :: "r"(addr + lo_off), "r"(v0), "r"(v1), "r"(v2), "r"(v3));
}
#define LDSM_X4(r0, r1, r2, r3, addr) \
    asm volatile("ldmatrix.sync.aligned.m8n8.x4.shared.b16 {%0,%1,%2,%3}, [%4];" \
        : "=r"(r0), "=r"(r1), "=r"(r2), "=r"(r3) : "r"(addr))
__device__ __forceinline__ void mma16816h(float d[4], const uint32_t a[4], const uint32_t b[2]) {
    asm volatile("mma.sync.aligned.m16n8k16.row.col.f32.f16.f16.f32 "
        "{%0,%1,%2,%3},{%4,%5,%6,%7},{%8,%9},{%0,%1,%2,%3};"
        : "+f"(d[0]), "+f"(d[1]), "+f"(d[2]), "+f"(d[3])
        : "r"(a[0]), "r"(a[1]), "r"(a[2]), "r"(a[3]), "r"(b[0]), "r"(b[1]));
}

// ============ fp16x3-split mma.sync GEMM, templated tile/epilogue ==========
// C[row, col] = sum_k A(row,k) * W(col,k) + bias[col]; optional gelu.
// A = A1 rows (lda1, K1 cols) concat A2 rows (lda2, K2 cols). K1,K2 % 32 == 0.
// block tile 128 x NT. grid (Ncols/NT, M/128, Z) with per-Z strides.
template<int NT, bool GELU>
__global__ __launch_bounds__(256, 2)
void mma_gemm(const float* __restrict__ A1, int lda1, int K1,
              const float* __restrict__ A2, int lda2, int K2,
              const float* __restrict__ W,
              const float* __restrict__ bias,
              float* __restrict__ C, int ldc,
              long long az, long long wz, long long bz, long long cz)
{
    constexpr uint32_t BLO = NT * 80;       // B lo-plane offset
    __shared__ __align__(128) uint8_t smem_raw[20480 + 2 * NT * 80];
    const uint32_t SA = smem_u32(smem_raw);
    const uint32_t SB = SA + 20480;
    const int Kt = K1 + K2;
    const int tid = threadIdx.x;
    const int wid = tid >> 5, lid = tid & 31;
    const int warp_m = wid & 3, warp_n = wid >> 2;
    const long long row0 = (long long)blockIdx.y * 128;
    const int col0 = blockIdx.x * NT;
    const int z = blockIdx.z;
    const float* A1z = A1 + (long long)z * az;
    const float* Wz  = W + (long long)z * wz;
    float* Cz = C + (long long)z * cz;

    const int lr = tid >> 1, kh = tid & 1;
    const uint32_t sAst = SA + (uint32_t)lr * 80 + (uint32_t)kh * 32;
    const uint32_t sBst = SB + (uint32_t)lr * 80 + (uint32_t)kh * 32;
    const bool bvalid = lr < NT;
    const float* Brow = bvalid ? (Wz + (long long)(col0 + lr) * Kt + kh * 16) : Wz;

    uint32_t aoff[2];
#pragma unroll
    for (int mt = 0; mt < 2; mt++) {
        int rowm = warp_m * 32 + mt * 16 + (lid & 7) + ((lid >> 3) & 1) * 8;
        aoff[mt] = SA + (uint32_t)rowm * 80 + (uint32_t)((lid >> 4) & 1) * 16;
    }
    constexpr int NTP = NT / 32;
    uint32_t boff[NTP];
#pragma unroll
    for (int ntp = 0; ntp < NTP; ntp++) {
        int rown = warp_n * (NT / 2) + ntp * 16 + (lid & 7) + ((lid >> 4) & 1) * 8;
        boff[ntp] = SB + (uint32_t)rown * 80 + (uint32_t)((lid >> 3) & 1) * 16;
    }

    float acc[2][NT / 16][4];
#pragma unroll
    for (int i = 0; i < 2; i++)
#pragma unroll
        for (int j = 0; j < NT / 16; j++)
#pragma unroll
            for (int q = 0; q < 4; q++) acc[i][j][q] = 0.f;

    const int nchunk = Kt >> 5;
    for (int ch = 0; ch < nchunk; ch++) {
        const int k0 = ch * 32;
        const float* Arow = (k0 < K1)
            ? A1z + (row0 + lr) * (long long)lda1 + k0 + kh * 16
            : A2  + (row0 + lr) * (long long)lda2 + (k0 - K1) + kh * 16;
        float4 a00 = *(const float4*)(Arow);
        float4 a01 = *(const float4*)(Arow + 4);
        float4 a10 = *(const float4*)(Arow + 8);
        float4 a11 = *(const float4*)(Arow + 12);
        float4 b00, b01, b10, b11;
        if (bvalid) {
            b00 = *(const float4*)(Brow + k0);
            b01 = *(const float4*)(Brow + k0 + 4);
            b10 = *(const float4*)(Brow + k0 + 8);
            b11 = *(const float4*)(Brow + k0 + 12);
        }
        __syncthreads();
        split8h(sAst,      10240, a00, a01);
        split8h(sAst + 16, 10240, a10, a11);
        if (bvalid) {
            split8h(sBst,      BLO, b00, b01);
            split8h(sBst + 16, BLO, b10, b11);
        }
        __syncthreads();

#pragma unroll
        for (int khalf = 0; khalf < 2; khalf++) {
            const uint32_t kb = (uint32_t)khalf * 32;
            uint32_t Ah[2][4], Al[2][4];
#pragma unroll
            for (int mt = 0; mt < 2; mt++) {
                LDSM_X4(Ah[mt][0], Ah[mt][1], Ah[mt][2], Ah[mt][3], aoff[mt] + kb);
                LDSM_X4(Al[mt][0], Al[mt][1], Al[mt][2], Al[mt][3], aoff[mt] + kb + 10240);
            }
#pragma unroll
            for (int ntp = 0; ntp < NTP; ntp++) {
                uint32_t Bh[4], Bl[4];
                LDSM_X4(Bh[0], Bh[1], Bh[2], Bh[3], boff[ntp] + kb);
                LDSM_X4(Bl[0], Bl[1], Bl[2], Bl[3], boff[ntp] + kb + BLO);
#pragma unroll
                for (int mt = 0; mt < 2; mt++) {
#pragma unroll
                    for (int nt2 = 0; nt2 < 2; nt2++) {
                        float* d = acc[mt][ntp * 2 + nt2];
                        mma16816h(d, Ah[mt], &Bh[nt2 * 2]);
                        mma16816h(d, Ah[mt], &Bl[nt2 * 2]);
                        mma16816h(d, Al[mt], &Bh[nt2 * 2]);
                    }
                }
            }
        }
    }

    const int g = lid >> 2, t = lid & 3;
    const float* biz = bias ? bias + (long long)z * bz : nullptr;
#pragma unroll
    for (int mt = 0; mt < 2; mt++) {
        long long rA = row0 + warp_m * 32 + mt * 16 + g;
        long long rB = rA + 8;
#pragma unroll
        for (int nt = 0; nt < NT / 16; nt++) {
            int col = col0 + warp_n * (NT / 2) + nt * 8 + 2 * t;
            float b0 = biz ? biz[col] : 0.f;
            float b1 = biz ? biz[col + 1] : 0.f;
            float* d = acc[mt][nt];
            float o0 = d[0] + b0, o1 = d[1] + b1, o2 = d[2] + b0, o3 = d[3] + b1;
            if (GELU) {
                o0 = 0.5f * o0 * (1.f + erff(o0 * 0.70710678118654752f));
                o1 = 0.5f * o1 * (1.f + erff(o1 * 0.70710678118654752f));
                o2 = 0.5f * o2 * (1.f + erff(o2 * 0.70710678118654752f));
                o3 = 0.5f * o3 * (1.f + erff(o3 * 0.70710678118654752f));
            }
            *(float2*)(Cz + rA * ldc + col) = make_float2(o0, o1);
            *(float2*)(Cz + rB * ldc + col) = make_float2(o2, o3);
        }
    }
}

// -------------------- Q = node[:, 0, :] @ Wq_w^T + Wq_b --------------------
__global__ __launch_bounds__(256)
void q_kernel(const float* __restrict__ node, const float* __restrict__ Wq_w,
              const float* __restrict__ Wq_b)
{
    __shared__ __align__(16) float xs[512];
    const int b = blockIdx.x, tid = threadIdx.x;
    const float* xr = node + (long long)b * Nn * Cc;
    xs[tid]       = xr[tid];
    xs[tid + 256] = xr[tid + 256];
    __syncthreads();
    const float4* x4 = (const float4*)xs;
    for (int j = tid; j < 512; j += 256) {
        const float4* w4 = (const float4*)(Wq_w + (long long)j * 512);
        float acc = Wq_b[j];
#pragma unroll 8
        for (int k = 0; k < 128; k++) {
            float4 w = w4[k], x = x4[k];
            acc += w.x*x.x + w.y*x.y + w.z*x.z + w.w*x.w;
        }
        g_Q[b * 512 + j] = acc;
    }
}

// ------ Weff[b,e2,:] = sum_a Q[b,a,e2] * Wk_w[a*64+e2,:]; beff similarly ----
__global__ __launch_bounds__(256)
void weff_kernel(const float* __restrict__ Wk_w, const float* __restrict__ Wk_b)
{
    __shared__ float Qs[512];
    const int b = blockIdx.x, tid = threadIdx.x;
    Qs[tid]       = g_Q[b * 512 + tid];
    Qs[tid + 256] = g_Q[b * 512 + 256 + tid];
    __syncthreads();
    for (int idx = tid; idx < 64 * 512; idx += 256) {
        int e2 = idx >> 9, c = idx & 511;
        float acc = 0.f;
#pragma unroll
        for (int a = 0; a < 8; a++)
            acc += Qs[a * 64 + e2] * Wk_w[(long long)(a * 64 + e2) * 512 + c];
        g_Weff[(long long)b * 32768 + idx] = acc;
    }
    if (tid < 64) {
        float acc = 0.f;
#pragma unroll
        for (int a = 0; a < 8; a++) acc += Qs[a * 64 + tid] * Wk_b[a * 64 + tid];
        g_beff[b * 64 + tid] = acc;
    }
}

// -------------------- weight prep ------------------------------------------
__global__ void prep12(const float* __restrict__ Wa_w1, const float* __restrict__ et_w1,
                       const float* __restrict__ et_b1)
{
    int i = blockIdx.x * 256 + threadIdx.x;
    if (i < 4096) {
        int h = i >> 5, k = i & 31;
        g_W12[i] = (h < 64) ? Wa_w1[h * 32 + k] : et_w1[(h - 64) * 32 + k];
    }
    if (i < 128) g_b12[i] = (i < 64) ? 0.f : et_b1[i - 64];
}
__global__ void prepsum(const float* __restrict__ nt_w, const float* __restrict__ nt_b,
                        const float* __restrict__ et_w2, const float* __restrict__ et_b2)
{
    int n = blockIdx.x, t = threadIdx.x;
    for (int k = t; k < 512; k += 256) g_Wsum[n * 576 + k] = nt_w[n * 512 + k];
    if (t < 64) g_Wsum[n * 576 + 512 + t] = et_w2[n * 64 + t];
    if (t == 0) g_bsum[n] = nt_b[n] + et_b2[n];
}

// -------------------- val = selu(rho(QKlo*ew) + QKhi*emb1 + emb2) ----------
__global__ __launch_bounds__(256)
void val_kernel(const float* __restrict__ edge, const float* __restrict__ emb1,
                const float* __restrict__ emb2, const float* __restrict__ Wew)
{
    __shared__ float WewT[32 * 32];   // [j][e]
    __shared__ float er[8][32];
    const int tid = threadIdx.x;
    const long long row0 = (long long)blockIdx.x * 8;
    for (int i = tid; i < 1024; i += 256) WewT[(i & 31) * 32 + (i >> 5)] = Wew[i];
    er[tid >> 5][tid & 31] = edge[row0 * 32 + tid];
    if (tid < 224) {  // remaining rows loaded by first 224 threads? no: 8*32=256 exactly
    }
    __syncthreads();

    const int r = tid >> 5, e = tid & 31;
    const long long row = row0 + r;
    float ew = 0.f;
#pragma unroll
    for (int j = 0; j < 32; j++) ew += er[r][j] * WewT[j * 32 + e];
    float qk  = g_QK[row * 64 + e];
    float qkh = g_QK[row * 64 + 32 + e];
    float x = qk * ew;
    float rr = (x > 0.f) ? sqrtf(x) : -sqrtf(-x);
    float v = rr + qkh * emb1[row * 32 + e] + emb2[row * 32 + e];
    const float sc = 1.0507009873554805f, al = 1.6732632423543772f;
    float s = (v > 0.f) ? sc * v : sc * al * (expf(v) - 1.f);
    g_val[row * 32 + e] = s;
}

// ---- fused tail: softmax over n, tmp=(sum)*alpha, threshold, mask, colsum --
// grid (4, 64): block owns (batch b, 128 channels). 512 thr = 16 n-slices x 32 lanes.
__global__ __launch_bounds__(512)
void tail_kernel(float* __restrict__ d_tmp, float* __restrict__ outp)
{
    __shared__ float4 redm[16][32];
    __shared__ float4 reds[16][32];
    const int b = blockIdx.y, cb = blockIdx.x;
    const int slice = threadIdx.x >> 5, lane = threadIdx.x & 31;
    const long long lgbase  = (long long)b * 2048 * 128 + cb * 32 + lane;
    const long long tmpbase = (long long)b * 2047 * 128 + cb * 32 + lane;
    const float4* LG = (const float4*)g_logits;
    const float4* SM = (const float4*)g_sum;
    float4* TMP = (float4*)d_tmp;
    const int n0 = 1 + slice * 128;
    const int n1 = min(2048, n0 + 128);

    // phase A: online softmax stats per channel
    float mx=-1e30f, my=-1e30f, mz=-1e30f, mw=-1e30f;
    float sx=0.f, sy=0.f, sz=0.f, sw=0.f;
#pragma unroll 4
    for (int n = n0; n < n1; n++) {
        float4 x = LG[lgbase + (long long)n * 128];
        if (x.x > mx) { sx = sx * expf(mx - x.x) + 1.f; mx = x.x; } else sx += expf(x.x - mx);
        if (x.y > my) { sy = sy * expf(my - x.y) + 1.f; my = x.y; } else sy += expf(x.y - my);
        if (x.z > mz) { sz = sz * expf(mz - x.z) + 1.f; mz = x.z; } else sz += expf(x.z - mz);
        if (x.w > mw) { sw = sw * expf(mw - x.w) + 1.f; mw = x.w; } else sw += expf(x.w - mw);
    }
    redm[slice][lane] = make_float4(mx, my, mz, mw);
    reds[slice][lane] = make_float4(sx, sy, sz, sw);
    __syncthreads();
    float Mx=-1e30f, My=-1e30f, Mz=-1e30f, Mw=-1e30f;
#pragma unroll
    for (int k = 0; k < 16; k++) {
        float4 fm = redm[k][lane];
        Mx = fmaxf(Mx, fm.x); My = fmaxf(My, fm.y);
        Mz = fmaxf(Mz, fm.z); Mw = fmaxf(Mw, fm.w);
    }
    float Sx=0.f, Sy=0.f, Sz=0.f, Sw=0.f;
#pragma unroll
    for (int k = 0; k < 16; k++) {
        float4 fm = redm[k][lane];
        float4 fs = reds[k][lane];
        Sx += fs.x * expf(fm.x - Mx); Sy += fs.y * expf(fm.y - My);
        Sz += fs.z * expf(fm.z - Mz); Sw += fs.w * expf(fm.w - Mw);
    }
    const float ivx = 1.f / Sx, ivy = 1.f / Sy, ivz = 1.f / Sz, ivw = 1.f / Sw;
    __syncthreads();

    // phase B: tmp = sum * alpha; column |max|
    float ax_=0.f, ay_=0.f, az_=0.f, aw_=0.f;
#pragma unroll 4
    for (int n = n0; n < n1; n++) {
        float4 x = LG[lgbase + (long long)n * 128];
        float4 sm = SM[lgbase + (long long)n * 128];
        float tx = sm.x * (expf(x.x - Mx) * ivx);
        float ty = sm.y * (expf(x.y - My) * ivy);
        float tz = sm.z * (expf(x.z - Mz) * ivz);
        float tw = sm.w * (expf(x.w - Mw) * ivw);
        TMP[tmpbase + (long long)(n - 1) * 128] = make_float4(tx, ty, tz, tw);
        ax_ = fmaxf(ax_, fabsf(tx)); ay_ = fmaxf(ay_, fabsf(ty));
        az_ = fmaxf(az_, fabsf(tz)); aw_ = fmaxf(aw_, fabsf(tw));
    }
    redm[slice][lane] = make_float4(ax_, ay_, az_, aw_);
    __syncthreads();
    float tx_=0.f, ty_=0.f, tz_=0.f, tw_=0.f;
#pragma unroll
    for (int k = 0; k < 16; k++) {
        float4 fm = redm[k][lane];
        tx_ = fmaxf(tx_, fm.x); ty_ = fmaxf(ty_, fm.y);
        tz_ = fmaxf(tz_, fm.z); tw_ = fmaxf(tw_, fm.w);
    }
    const float thx = tx_ * 0.1f, thy = ty_ * 0.1f, thz = tz_ * 0.1f, thw = tw_ * 0.1f;
    __syncthreads();

    // phase C: mask in place, column sum
    float cx=0.f, cy=0.f, cz2=0.f, cw=0.f;
#pragma unroll 4
    for (int n = n0; n < n1; n++) {
        float4 t = TMP[tmpbase + (long long)(n - 1) * 128];
        t.x = (fabsf(t.x) >= thx) ? t.x : 0.f;
        t.y = (fabsf(t.y) >= thy) ? t.y : 0.f;
        t.z = (fabsf(t.z) >= thz) ? t.z : 0.f;
        t.w = (fabsf(t.w) >= thw) ? t.w : 0.f;
        TMP[tmpbase + (long long)(n - 1) * 128] = t;
        cx += t.x; cy += t.y; cz2 += t.z; cw += t.w;
    }
    redm[slice][lane] = make_float4(cx, cy, cz2, cw);
    __syncthreads();
    if (slice == 0) {
        float4 tot = make_float4(0.f, 0.f, 0.f, 0.f);
#pragma unroll
        for (int k = 0; k < 16; k++) {
            float4 f = redm[k][lane];
            tot.x += f.x; tot.y += f.y; tot.z += f.z; tot.w += f.w;
        }
        ((float4*)outp)[(long long)b * 128 + cb * 32 + lane] = tot;
    }
}

// ---------------------------------------------------------------------------
extern "C" void kernel_launch(void* const* d_in, const int* in_sizes, int n_in,
                              void* d_out, int out_size)
{
    const float* node  = (const float*)d_in[0];
    const float* edge  = (const float*)d_in[1];
    const float* emb1  = (const float*)d_in[2];
    const float* emb2  = (const float*)d_in[3];
    const float* Wq_w  = (const float*)d_in[4];
    const float* Wq_b  = (const float*)d_in[5];
    const float* Wk_w  = (const float*)d_in[6];
    const float* Wk_b  = (const float*)d_in[7];
    const float* Wew_w = (const float*)d_in[8];
    const float* Wa_w1 = (const float*)d_in[9];
    const float* Wa_w2 = (const float*)d_in[10];
    const float* nt_w  = (const float*)d_in[11];
    const float* nt_b  = (const float*)d_in[12];
    const float* et_w1 = (const float*)d_in[13];
    const float* et_b1 = (const float*)d_in[14];
    const float* et_w2 = (const float*)d_in[15];
    const float* et_b2 = (const float*)d_in[16];

    float* outp  = (float*)d_out;            // (B, IN) first
    float* d_tmp = outp + Bb * INc;          // then (B, N-1, IN)

    void *pSum, *pLG, *pH12, *pQK, *pVal, *pWeff, *pBeff, *pW12, *pB12, *pWsum, *pBsum;
    cudaGetSymbolAddress(&pSum,  g_sum);
    cudaGetSymbolAddress(&pLG,   g_logits);
    cudaGetSymbolAddress(&pH12,  g_H12);
    cudaGetSymbolAddress(&pQK,   g_QK);
    cudaGetSymbolAddress(&pVal,  g_val);
    cudaGetSymbolAddress(&pWeff, g_Weff);
    cudaGetSymbolAddress(&pBeff, g_beff);
    cudaGetSymbolAddress(&pW12,  g_W12);
    cudaGetSymbolAddress(&pB12,  g_b12);
    cudaGetSymbolAddress(&pWsum, g_Wsum);
    cudaGetSymbolAddress(&pBsum, g_bsum);

    // weight prep (independent)
    prep12<<<16, 256>>>(Wa_w1, et_w1, et_b1);
    prepsum<<<512, 256>>>(nt_w, nt_b, et_w2, et_b2);

    // Q -> Weff/beff -> QK (batched N=64 GEMM, K=512)
    q_kernel<<<Bb, 256>>>(node, Wq_w, Wq_b);
    weff_kernel<<<Bb, 256>>>(Wk_w, Wk_b);
    mma_gemm<64, false><<<dim3(1, Nn / 128, Bb), 256>>>(
        node, Cc, Cc, nullptr, 0, 0,
        (const float*)pWeff, (const float*)pBeff, (float*)pQK, 64,
        (long long)Nn * Cc, 64LL * 512, 64LL, (long long)Nn * 64);

    // val
    val_kernel<<<Mtot / 8, 256>>>(edge, emb1, emb2, Wew_w);

    // H12 = gelu(val @ W12^T + b12)   (M x 128, K=32)
    mma_gemm<128, true><<<dim3(1, Mtot / 128, 1), 256>>>(
        (const float*)pVal, 32, 32, nullptr, 0, 0,
        (const float*)pW12, (const float*)pB12, (float*)pH12, 128, 0, 0, 0, 0);

    // logits = H1 @ Wa_w2^T           (M x 512, K=64)
    mma_gemm<128, false><<<dim3(4, Mtot / 128, 1), 256>>>(
        (const float*)pH12, 128, 64, nullptr, 0, 0,
        Wa_w2, nullptr, (float*)pLG, INc, 0, 0, 0, 0);

    // sum = node @ nt_w^T + H2 @ et_w2^T + (nt_b + et_b2)   (M x 512, K=576)
    mma_gemm<128, false><<<dim3(4, Mtot / 128, 1), 256>>>(
        node, Cc, Cc, (const float*)pH12 + 64, 128, 64,
        (const float*)pWsum, (const float*)pBsum, (float*)pSum, INc, 0, 0, 0, 0);

    // fused softmax + combine + threshold + mask + colsum
    tail_kernel<<<dim3(4, Bb), 512>>>(d_tmp, outp);
}

// round 6
// speedup vs baseline: 2.6333x; 1.0090x over previous
#include <cuda_runtime.h>
#include <cuda_fp16.h>
#include <math.h>
#include <stdint.h>

#define Bb   64
#define Nn   2048
#define Cc   512
#define Ee   32
#define Ac   8
#define INc  512
#define Hc   64
#define Mtot (Bb*Nn)

// -------------------- device scratch (static; allocation-free) -------------
__device__ float g_sum    [(long long)Mtot*INc];   // node_t + edge_t (pre-alpha)
__device__ float g_logits [(long long)Mtot*INc];
__device__ float g_H12    [(long long)Mtot*128];   // [H1 | H2]
__device__ float g_QK     [(long long)Mtot*64];
__device__ float g_val    [(long long)Mtot*Ee];
__device__ float g_Weff   [Bb*64*512];
__device__ float g_beff   [Bb*64];
__device__ float g_Q      [Bb*512];
__device__ float g_W12    [128*32];
__device__ float g_b12    [128];
__device__ float g_Wsum   [512*576];
__device__ float g_bsum   [512];

// ========================== helpers ========================================
__device__ __forceinline__ uint32_t smem_u32(const void* p) {
    uint32_t a;
    asm("{ .reg .u64 t; cvta.to.shared.u64 t, %1; cvt.u32.u64 %0, t; }" : "=r"(a) : "l"(p));
    return a;
}
// 8 fp32 -> hi f16x8 (16B at addr), lo f16x8 (16B at addr+lo_off)
__device__ __forceinline__ void split8h(uint32_t addr, uint32_t lo_off, float4 a0, float4 a1) {
    __half2 h0 = __float22half2_rn(make_float2(a0.x, a0.y));
    __half2 h1 = __float22half2_rn(make_float2(a0.z, a0.w));
    __half2 h2 = __float22half2_rn(make_float2(a1.x, a1.y));
    __half2 h3 = __float22half2_rn(make_float2(a1.z, a1.w));
    float2 f0 = __half22float2(h0), f1 = __half22float2(h1);
    float2 f2 = __half22float2(h2), f3 = __half22float2(h3);
    __half2 l0 = __float22half2_rn(make_float2(a0.x - f0.x, a0.y - f0.y));
    __half2 l1 = __float22half2_rn(make_float2(a0.z - f1.x, a0.w - f1.y));
    __half2 l2 = __float22half2_rn(make_float2(a1.x - f2.x, a1.y - f2.y));
    __half2 l3 = __float22half2_rn(make_float2(a1.z - f3.x, a1.w - f3.y));
    uint32_t u0 = *(uint32_t*)&h0, u1 = *(uint32_t*)&h1, u2 = *(uint32_t*)&h2, u3 = *(uint32_t*)&h3;
    uint32_t v0 = *(uint32_t*)&l0, v1 = *(uint32_t*)&l1, v2 = *(uint32_t*)&l2, v3 = *(uint32_t*)&l3;
    asm volatile("st.shared.v4.b32 [%0], {%1,%2,%3,%4};" :: "r"(addr), "r"(u0), "r"(u1), "r"(u2), "r"(u3));
    asm volatile("st.shared.v4.b32 [%0], {%1,%2,%3,%4};" :: "r"(addr + lo_off), "r"(v0), "r"(v1), "r"(v2), "r"(v3));
}
#define LDSM_X4(r0, r1, r2, r3, addr) \
    asm volatile("ldmatrix.sync.aligned.m8n8.x4.shared.b16 {%0,%1,%2,%3}, [%4];" \
        : "=r"(r0), "=r"(r1), "=r"(r2), "=r"(r3) : "r"(addr))
__device__ __forceinline__ void mma16816h(float d[4], const uint32_t a[4], const uint32_t b[2]) {
    asm volatile("mma.sync.aligned.m16n8k16.row.col.f32.f16.f16.f32 "
        "{%0,%1,%2,%3},{%4,%5,%6,%7},{%8,%9},{%0,%1,%2,%3};"
        : "+f"(d[0]), "+f"(d[1]), "+f"(d[2]), "+f"(d[3])
        : "r"(a[0]), "r"(a[1]), "r"(a[2]), "r"(a[3]), "r"(b[0]), "r"(b[1]));
}

// ============ fp16x3-split mma.sync GEMM, templated tile/epilogue ==========
// C[row, col] = sum_k A(row,k) * W(col,k) + bias[col]; optional gelu.
// A = A1 rows (lda1, K1 cols) concat A2 rows (lda2, K2 cols). K1,K2 % 32 == 0.
// block tile 128 x NT. grid (Ncols/NT, M/128, Z) with per-Z strides.
template<int NT, bool GELU>
__global__ __launch_bounds__(256, 2)
void mma_gemm(const float* __restrict__ A1, int lda1, int K1,
              const float* __restrict__ A2, int lda2, int K2,
              const float* __restrict__ W,
              const float* __restrict__ bias,
              float* __restrict__ C, int ldc,
              long long az, long long wz, long long bz, long long cz)
{
    constexpr uint32_t BLO = NT * 80;       // B lo-plane offset
    __shared__ __align__(128) uint8_t smem_raw[20480 + 2 * NT * 80];
    const uint32_t SA = smem_u32(smem_raw);
    const uint32_t SB = SA + 20480;
    const int Kt = K1 + K2;
    const int tid = threadIdx.x;
    const int wid = tid >> 5, lid = tid & 31;
    const int warp_m = wid & 3, warp_n = wid >> 2;
    const long long row0 = (long long)blockIdx.y * 128;
    const int col0 = blockIdx.x * NT;
    const int z = blockIdx.z;
    const float* A1z = A1 + (long long)z * az;
    const float* Wz  = W + (long long)z * wz;
    float* Cz = C + (long long)z * cz;

    const int lr = tid >> 1, kh = tid & 1;
    const uint32_t sAst = SA + (uint32_t)lr * 80 + (uint32_t)kh * 32;
    const uint32_t sBst = SB + (uint32_t)lr * 80 + (uint32_t)kh * 32;
    const bool bvalid = lr < NT;
    const float* Brow = bvalid ? (Wz + (long long)(col0 + lr) * Kt + kh * 16) : Wz;

    uint32_t aoff[2];
#pragma unroll
    for (int mt = 0; mt < 2; mt++) {
        int rowm = warp_m * 32 + mt * 16 + (lid & 7) + ((lid >> 3) & 1) * 8;
        aoff[mt] = SA + (uint32_t)rowm * 80 + (uint32_t)((lid >> 4) & 1) * 16;
    }
    constexpr int NTP = NT / 32;
    uint32_t boff[NTP];
#pragma unroll
    for (int ntp = 0; ntp < NTP; ntp++) {
        int rown = warp_n * (NT / 2) + ntp * 16 + (lid & 7) + ((lid >> 4) & 1) * 8;
        boff[ntp] = SB + (uint32_t)rown * 80 + (uint32_t)((lid >> 3) & 1) * 16;
    }

    float acc[2][NT / 16][4];
#pragma unroll
    for (int i = 0; i < 2; i++)
#pragma unroll
        for (int j = 0; j < NT / 16; j++)
#pragma unroll
            for (int q = 0; q < 4; q++) acc[i][j][q] = 0.f;

    const int nchunk = Kt >> 5;

    // prefetch chunk 0 into registers
    float4 a00, a01, a10, a11, b00, b01, b10, b11;
    {
        const float* Arow = A1z + (row0 + lr) * (long long)lda1 + kh * 16;
        a00 = *(const float4*)(Arow);
        a01 = *(const float4*)(Arow + 4);
        a10 = *(const float4*)(Arow + 8);
        a11 = *(const float4*)(Arow + 12);
        if (bvalid) {
            b00 = *(const float4*)(Brow);
            b01 = *(const float4*)(Brow + 4);
            b10 = *(const float4*)(Brow + 8);
            b11 = *(const float4*)(Brow + 12);
        }
    }

    for (int ch = 0; ch < nchunk; ch++) {
        __syncthreads();
        split8h(sAst,      10240, a00, a01);
        split8h(sAst + 16, 10240, a10, a11);
        if (bvalid) {
            split8h(sBst,      BLO, b00, b01);
            split8h(sBst + 16, BLO, b10, b11);
        }
        __syncthreads();

        // prefetch next chunk (gmem latency hides behind MMAs below)
        if (ch + 1 < nchunk) {
            const int k0 = (ch + 1) * 32;
            const float* Arow = (k0 < K1)
                ? A1z + (row0 + lr) * (long long)lda1 + k0 + kh * 16
                : A2  + (row0 + lr) * (long long)lda2 + (k0 - K1) + kh * 16;
            a00 = *(const float4*)(Arow);
            a01 = *(const float4*)(Arow + 4);
            a10 = *(const float4*)(Arow + 8);
            a11 = *(const float4*)(Arow + 12);
            if (bvalid) {
                b00 = *(const float4*)(Brow + k0);
                b01 = *(const float4*)(Brow + k0 + 4);
                b10 = *(const float4*)(Brow + k0 + 8);
                b11 = *(const float4*)(Brow + k0 + 12);
            }
        }

#pragma unroll
        for (int khalf = 0; khalf < 2; khalf++) {
            const uint32_t kb = (uint32_t)khalf * 32;
            uint32_t Ah[2][4], Al[2][4];
#pragma unroll
            for (int mt = 0; mt < 2; mt++) {
                LDSM_X4(Ah[mt][0], Ah[mt][1], Ah[mt][2], Ah[mt][3], aoff[mt] + kb);
                LDSM_X4(Al[mt][0], Al[mt][1], Al[mt][2], Al[mt][3], aoff[mt] + kb + 10240);
            }
#pragma unroll
            for (int ntp = 0; ntp < NTP; ntp++) {
                uint32_t Bh[4], Bl[4];
                LDSM_X4(Bh[0], Bh[1], Bh[2], Bh[3], boff[ntp] + kb);
                LDSM_X4(Bl[0], Bl[1], Bl[2], Bl[3], boff[ntp] + kb + BLO);
#pragma unroll
                for (int mt = 0; mt < 2; mt++) {
#pragma unroll
                    for (int nt2 = 0; nt2 < 2; nt2++) {
                        float* d = acc[mt][ntp * 2 + nt2];
                        mma16816h(d, Ah[mt], &Bh[nt2 * 2]);
                        mma16816h(d, Ah[mt], &Bl[nt2 * 2]);
                        mma16816h(d, Al[mt], &Bh[nt2 * 2]);
                    }
                }
            }
        }
    }

    const int g = lid >> 2, t = lid & 3;
    const float* biz = bias ? bias + (long long)z * bz : nullptr;
#pragma unroll
    for (int mt = 0; mt < 2; mt++) {
        long long rA = row0 + warp_m * 32 + mt * 16 + g;
        long long rB = rA + 8;
#pragma unroll
        for (int nt = 0; nt < NT / 16; nt++) {
            int col = col0 + warp_n * (NT / 2) + nt * 8 + 2 * t;
            float b0 = biz ? biz[col] : 0.f;
            float b1 = biz ? biz[col + 1] : 0.f;
            float* d = acc[mt][nt];
            float o0 = d[0] + b0, o1 = d[1] + b1, o2 = d[2] + b0, o3 = d[3] + b1;
            if (GELU) {
                o0 = 0.5f * o0 * (1.f + erff(o0 * 0.70710678118654752f));
                o1 = 0.5f * o1 * (1.f + erff(o1 * 0.70710678118654752f));
                o2 = 0.5f * o2 * (1.f + erff(o2 * 0.70710678118654752f));
                o3 = 0.5f * o3 * (1.f + erff(o3 * 0.70710678118654752f));
            }
            *(float2*)(Cz + rA * ldc + col) = make_float2(o0, o1);
            *(float2*)(Cz + rB * ldc + col) = make_float2(o2, o3);
        }
    }
}

// -------------------- Q = node[:, 0, :] @ Wq_w^T + Wq_b --------------------
__global__ __launch_bounds__(256)
void q_kernel(const float* __restrict__ node, const float* __restrict__ Wq_w,
              const float* __restrict__ Wq_b)
{
    __shared__ __align__(16) float xs[512];
    const int b = blockIdx.x, tid = threadIdx.x;
    const float* xr = node + (long long)b * Nn * Cc;
    xs[tid]       = xr[tid];
    xs[tid + 256] = xr[tid + 256];
    __syncthreads();
    const float4* x4 = (const float4*)xs;
    for (int j = tid; j < 512; j += 256) {
        const float4* w4 = (const float4*)(Wq_w + (long long)j * 512);
        float acc = Wq_b[j];
#pragma unroll 8
        for (int k = 0; k < 128; k++) {
            float4 w = w4[k], x = x4[k];
            acc += w.x*x.x + w.y*x.y + w.z*x.z + w.w*x.w;
        }
        g_Q[b * 512 + j] = acc;
    }
}

// ------ Weff[b,e2,:] = sum_a Q[b,a,e2] * Wk_w[a*64+e2,:]; beff similarly ----
// grid (Bb, 8): each block does 4096 of the 32768 outputs for batch b.
__global__ __launch_bounds__(256)
void weff_kernel(const float* __restrict__ Wk_w, const float* __restrict__ Wk_b)
{
    __shared__ float Qs[512];
    const int b = blockIdx.x, part = blockIdx.y, tid = threadIdx.x;
    Qs[tid]       = g_Q[b * 512 + tid];
    Qs[tid + 256] = g_Q[b * 512 + 256 + tid];
    __syncthreads();
    const int i0 = part * 4096;
    for (int idx = i0 + tid; idx < i0 + 4096; idx += 256) {
        int e2 = idx >> 9, c = idx & 511;
        float acc = 0.f;
#pragma unroll
        for (int a = 0; a < 8; a++)
            acc += Qs[a * 64 + e2] * Wk_w[(long long)(a * 64 + e2) * 512 + c];
        g_Weff[(long long)b * 32768 + idx] = acc;
    }
    if (part == 0 && tid < 64) {
        float acc = 0.f;
#pragma unroll
        for (int a = 0; a < 8; a++) acc += Qs[a * 64 + tid] * Wk_b[a * 64 + tid];
        g_beff[b * 64 + tid] = acc;
    }
}

// -------------------- weight prep ------------------------------------------
__global__ void prep12(const float* __restrict__ Wa_w1, const float* __restrict__ et_w1,
                       const float* __restrict__ et_b1)
{
    int i = blockIdx.x * 256 + threadIdx.x;
    if (i < 4096) {
        int h = i >> 5, k = i & 31;
        g_W12[i] = (h < 64) ? Wa_w1[h * 32 + k] : et_w1[(h - 64) * 32 + k];
    }
    if (i < 128) g_b12[i] = (i < 64) ? 0.f : et_b1[i - 64];
}
__global__ void prepsum(const float* __restrict__ nt_w, const float* __restrict__ nt_b,
                        const float* __restrict__ et_w2, const float* __restrict__ et_b2)
{
    int n = blockIdx.x, t = threadIdx.x;
    for (int k = t; k < 512; k += 256) g_Wsum[n * 576 + k] = nt_w[n * 512 + k];
    if (t < 64) g_Wsum[n * 576 + 512 + t] = et_w2[n * 64 + t];
    if (t == 0) g_bsum[n] = nt_b[n] + et_b2[n];
}

// -------------------- val = selu(rho(QKlo*ew) + QKhi*emb1 + emb2) ----------
__global__ __launch_bounds__(256)
void val_kernel(const float* __restrict__ edge, const float* __restrict__ emb1,
                const float* __restrict__ emb2, const float* __restrict__ Wew)
{
    __shared__ float WewT[32 * 32];   // [j][e]
    __shared__ float er[8][32];
    const int tid = threadIdx.x;
    const long long row0 = (long long)blockIdx.x * 8;
    for (int i = tid; i < 1024; i += 256) WewT[(i & 31) * 32 + (i >> 5)] = Wew[i];
    er[tid >> 5][tid & 31] = edge[row0 * 32 + tid];
    __syncthreads();

    const int r = tid >> 5, e = tid & 31;
    const long long row = row0 + r;
    float ew = 0.f;
#pragma unroll
    for (int j = 0; j < 32; j++) ew += er[r][j] * WewT[j * 32 + e];
    float qk  = g_QK[row * 64 + e];
    float qkh = g_QK[row * 64 + 32 + e];
    float x = qk * ew;
    float rr = (x > 0.f) ? sqrtf(x) : -sqrtf(-x);
    float v = rr + qkh * emb1[row * 32 + e] + emb2[row * 32 + e];
    const float sc = 1.0507009873554805f, al = 1.6732632423543772f;
    float s = (v > 0.f) ? sc * v : sc * al * (expf(v) - 1.f);
    g_val[row * 32 + e] = s;
}

// ---- fused tail v2: 2 passes over (logits, sum), single tmp write ---------
// grid (4, 64): block owns (batch b, 128 channels). 512 thr = 16 n-slices x 32 lanes.
// Pass A: online softmax stats + max|u| (u = sm*exp(x-m), rescaled online).
// Pass B: recompute t = sm*exp(x-M)/S, mask via |u| >= U/10, write once, colsum.
__global__ __launch_bounds__(512)
void tail_kernel(float* __restrict__ d_tmp, float* __restrict__ outp)
{
    __shared__ float4 redm[16][32];
    __shared__ float4 reds[16][32];
    __shared__ float4 redu[16][32];
    const int b = blockIdx.y, cb = blockIdx.x;
    const int slice = threadIdx.x >> 5, lane = threadIdx.x & 31;
    const long long lgbase  = (long long)b * 2048 * 128 + cb * 32 + lane;
    const long long tmpbase = (long long)b * 2047 * 128 + cb * 32 + lane;
    const float4* LG = (const float4*)g_logits;
    const float4* SM = (const float4*)g_sum;
    float4* TMP = (float4*)d_tmp;
    const int n0 = 1 + slice * 128;
    const int n1 = min(2048, n0 + 128);

    // ---- pass A: softmax stats + unnormalized |max|
    float mx=-1e30f, my=-1e30f, mz=-1e30f, mw=-1e30f;
    float sx=0.f, sy=0.f, sz=0.f, sw=0.f;
    float ux=0.f, uy=0.f, uz=0.f, uw=0.f;
#pragma unroll 4
    for (int n = n0; n < n1; n++) {
        float4 x  = LG[lgbase + (long long)n * 128];
        float4 sm = SM[lgbase + (long long)n * 128];
        if (x.x > mx) { float f = expf(mx - x.x); sx = sx * f + 1.f; ux = fmaxf(ux * f, fabsf(sm.x)); mx = x.x; }
        else          { float e = expf(x.x - mx); sx += e; ux = fmaxf(ux, fabsf(sm.x) * e); }
        if (x.y > my) { float f = expf(my - x.y); sy = sy * f + 1.f; uy = fmaxf(uy * f, fabsf(sm.y)); my = x.y; }
        else          { float e = expf(x.y - my); sy += e; uy = fmaxf(uy, fabsf(sm.y) * e); }
        if (x.z > mz) { float f = expf(mz - x.z); sz = sz * f + 1.f; uz = fmaxf(uz * f, fabsf(sm.z)); mz = x.z; }
        else          { float e = expf(x.z - mz); sz += e; uz = fmaxf(uz, fabsf(sm.z) * e); }
        if (x.w > mw) { float f = expf(mw - x.w); sw = sw * f + 1.f; uw = fmaxf(uw * f, fabsf(sm.w)); mw = x.w; }
        else          { float e = expf(x.w - mw); sw += e; uw = fmaxf(uw, fabsf(sm.w) * e); }
    }
    redm[slice][lane] = make_float4(mx, my, mz, mw);
    reds[slice][lane] = make_float4(sx, sy, sz, sw);
    redu[slice][lane] = make_float4(ux, uy, uz, uw);
    __syncthreads();
    float Mx=-1e30f, My=-1e30f, Mz=-1e30f, Mw=-1e30f;
#pragma unroll
    for (int k = 0; k < 16; k++) {
        float4 fm = redm[k][lane];
        Mx = fmaxf(Mx, fm.x); My = fmaxf(My, fm.y);
        Mz = fmaxf(Mz, fm.z); Mw = fmaxf(Mw, fm.w);
    }
    float Sx=0.f, Sy=0.f, Sz=0.f, Sw=0.f;
    float Ux=0.f, Uy=0.f, Uz=0.f, Uw=0.f;
#pragma unroll
    for (int k = 0; k < 16; k++) {
        float4 fm = redm[k][lane];
        float4 fs = reds[k][lane];
        float4 fu = redu[k][lane];
        float ex = expf(fm.x - Mx), ey = expf(fm.y - My);
        float ez = expf(fm.z - Mz), ew = expf(fm.w - Mw);
        Sx += fs.x * ex; Sy += fs.y * ey; Sz += fs.z * ez; Sw += fs.w * ew;
        Ux = fmaxf(Ux, fu.x * ex); Uy = fmaxf(Uy, fu.y * ey);
        Uz = fmaxf(Uz, fu.z * ez); Uw = fmaxf(Uw, fu.w * ew);
    }
    const float ivx = 1.f / Sx, ivy = 1.f / Sy, ivz = 1.f / Sz, ivw = 1.f / Sw;
    const float tux = Ux * 0.1f, tuy = Uy * 0.1f, tuz = Uz * 0.1f, tuw = Uw * 0.1f;

    // ---- pass B: recompute, mask, single write, colsum
    float cx=0.f, cy=0.f, cz2=0.f, cw=0.f;
#pragma unroll 4
    for (int n = n0; n < n1; n++) {
        float4 x  = LG[lgbase + (long long)n * 128];
        float4 sm = SM[lgbase + (long long)n * 128];
        float ex = expf(x.x - Mx), ey = expf(x.y - My);
        float ez = expf(x.z - Mz), ew = expf(x.w - Mw);
        float uxx = sm.x * ex, uyy = sm.y * ey, uzz = sm.z * ez, uww = sm.w * ew;
        float tx = (fabsf(uxx) >= tux) ? uxx * ivx : 0.f;
        float ty = (fabsf(uyy) >= tuy) ? uyy * ivy : 0.f;
        float tz = (fabsf(uzz) >= tuz) ? uzz * ivz : 0.f;
        float tw = (fabsf(uww) >= tuw) ? uww * ivw : 0.f;
        TMP[tmpbase + (long long)(n - 1) * 128] = make_float4(tx, ty, tz, tw);
        cx += tx; cy += ty; cz2 += tz; cw += tw;
    }
    redm[slice][lane] = make_float4(cx, cy, cz2, cw);
    __syncthreads();
    if (slice == 0) {
        float4 tot = make_float4(0.f, 0.f, 0.f, 0.f);
#pragma unroll
        for (int k = 0; k < 16; k++) {
            float4 f = redm[k][lane];
            tot.x += f.x; tot.y += f.y; tot.z += f.z; tot.w += f.w;
        }
        ((float4*)outp)[(long long)b * 128 + cb * 32 + lane] = tot;
    }
}

// ---------------------------------------------------------------------------
extern "C" void kernel_launch(void* const* d_in, const int* in_sizes, int n_in,
                              void* d_out, int out_size)
{
    const float* node  = (const float*)d_in[0];
    const float* edge  = (const float*)d_in[1];
    const float* emb1  = (const float*)d_in[2];
    const float* emb2  = (const float*)d_in[3];
    const float* Wq_w  = (const float*)d_in[4];
    const float* Wq_b  = (const float*)d_in[5];
    const float* Wk_w  = (const float*)d_in[6];
    const float* Wk_b  = (const float*)d_in[7];
    const float* Wew_w = (const float*)d_in[8];
    const float* Wa_w1 = (const float*)d_in[9];
    const float* Wa_w2 = (const float*)d_in[10];
    const float* nt_w  = (const float*)d_in[11];
    const float* nt_b  = (const float*)d_in[12];
    const float* et_w1 = (const float*)d_in[13];
    const float* et_b1 = (const float*)d_in[14];
    const float* et_w2 = (const float*)d_in[15];
    const float* et_b2 = (const float*)d_in[16];

    float* outp  = (float*)d_out;            // (B, IN) first
    float* d_tmp = outp + Bb * INc;          // then (B, N-1, IN)

    void *pSum, *pLG, *pH12, *pQK, *pVal, *pWeff, *pBeff, *pW12, *pB12, *pWsum, *pBsum;
    cudaGetSymbolAddress(&pSum,  g_sum);
    cudaGetSymbolAddress(&pLG,   g_logits);
    cudaGetSymbolAddress(&pH12,  g_H12);
    cudaGetSymbolAddress(&pQK,   g_QK);
    cudaGetSymbolAddress(&pVal,  g_val);
    cudaGetSymbolAddress(&pWeff, g_Weff);
    cudaGetSymbolAddress(&pBeff, g_beff);
    cudaGetSymbolAddress(&pW12,  g_W12);
    cudaGetSymbolAddress(&pB12,  g_b12);
    cudaGetSymbolAddress(&pWsum, g_Wsum);
    cudaGetSymbolAddress(&pBsum, g_bsum);

    // weight prep (independent)
    prep12<<<16, 256>>>(Wa_w1, et_w1, et_b1);
    prepsum<<<512, 256>>>(nt_w, nt_b, et_w2, et_b2);

    // Q -> Weff/beff -> QK (batched N=64 GEMM, K=512)
    q_kernel<<<Bb, 256>>>(node, Wq_w, Wq_b);
    weff_kernel<<<dim3(Bb, 8), 256>>>(Wk_w, Wk_b);
    mma_gemm<64, false><<<dim3(1, Nn / 128, Bb), 256>>>(
        node, Cc, Cc, nullptr, 0, 0,
        (const float*)pWeff, (const float*)pBeff, (float*)pQK, 64,
        (long long)Nn * Cc, 64LL * 512, 64LL, (long long)Nn * 64);

    // val
    val_kernel<<<Mtot / 8, 256>>>(edge, emb1, emb2, Wew_w);

    // H12 = gelu(val @ W12^T + b12)   (M x 128, K=32)
    mma_gemm<128, true><<<dim3(1, Mtot / 128, 1), 256>>>(
        (const float*)pVal, 32, 32, nullptr, 0, 0,
        (const float*)pW12, (const float*)pB12, (float*)pH12, 128, 0, 0, 0, 0);

    // logits = H1 @ Wa_w2^T           (M x 512, K=64)
    mma_gemm<128, false><<<dim3(4, Mtot / 128, 1), 256>>>(
        (const float*)pH12, 128, 64, nullptr, 0, 0,
        Wa_w2, nullptr, (float*)pLG, INc, 0, 0, 0, 0);

    // sum = node @ nt_w^T + H2 @ et_w2^T + (nt_b + et_b2)   (M x 512, K=576)
    mma_gemm<128, false><<<dim3(4, Mtot / 128, 1), 256>>>(
        node, Cc, Cc, (const float*)pH12 + 64, 128, 64,
        (const float*)pWsum, (const float*)pBsum, (float*)pSum, INc, 0, 0, 0, 0);

    // fused softmax + combine + threshold + mask + colsum (2-pass recompute)
    tail_kernel<<<dim3(4, Bb), 512>>>(d_tmp, outp);
}